// round 2
// baseline (speedup 1.0000x reference)
#include <cuda_runtime.h>
#include <cstdint>

// ---------------- problem constants ----------------
#define S_    2048
#define N_    8
#define E_    512
#define C_    1024
#define G_    32
#define CG_   32
#define TOK_  (S_ * N_)          // 16384 tokens
#define LN_EPS 1e-5f

// ---------------- scratch (device globals; no allocations allowed) --------
__device__ float g_logits[(size_t)TOK_ * C_];   // 64 MB
__device__ float g_W2T[(size_t)C_ * E_];        // 2 MB  (W2 transposed: [c][e])

// ---------------- kernel 0: transpose W2 (E x C) -> W2T (C x E) -----------
__global__ void transpose_k(const float* __restrict__ W2) {
    __shared__ float tile[32][33];
    int c = blockIdx.x * 32 + threadIdx.x;   // col in W2
    int e = blockIdx.y * 32 + threadIdx.y;   // row in W2
    tile[threadIdx.y][threadIdx.x] = W2[(size_t)e * C_ + c];
    __syncthreads();
    int e2 = blockIdx.y * 32 + threadIdx.x;
    int c2 = blockIdx.x * 32 + threadIdx.y;
    g_W2T[(size_t)c2 * E_ + e2] = tile[threadIdx.x][threadIdx.y];
}

// ---------------- kernel 1: fp32 SGEMM  logits = 3*(x @ W1^T) + 3*b1 + off
// A = x    [M=16384, K=512] row-major
// B = W1   [N=1024,  K=512] row-major   (NT gemm)
// 128x128 block tile, BK=8, 256 threads, 8x8 per-thread microtile
__global__ void __launch_bounds__(256, 2)
gemm1_k(const float* __restrict__ A, const float* __restrict__ B,
        const float* __restrict__ b1, const float* __restrict__ coff)
{
    constexpr int K = E_;
    __shared__ float As[8][128];
    __shared__ float Bs[8][128];
    const int tid  = threadIdx.x;
    const int m0   = blockIdx.y * 128;
    const int n0   = blockIdx.x * 128;
    const int lrow = tid >> 1;          // 0..127
    const int lcol = (tid & 1) * 4;     // 0 or 4
    const int tx   = tid & 15;          // n-subtile
    const int ty   = tid >> 4;          // m-subtile

    const float* Aptr = A + (size_t)(m0 + lrow) * K + lcol;
    const float* Bptr = B + (size_t)(n0 + lrow) * K + lcol;

    float4 av = *(const float4*)Aptr;
    float4 bv = *(const float4*)Bptr;

    float acc[8][8];
    #pragma unroll
    for (int i = 0; i < 8; i++)
        #pragma unroll
        for (int j = 0; j < 8; j++) acc[i][j] = 0.0f;

    for (int k0 = 0; k0 < K; k0 += 8) {
        __syncthreads();
        As[lcol + 0][lrow] = av.x; As[lcol + 1][lrow] = av.y;
        As[lcol + 2][lrow] = av.z; As[lcol + 3][lrow] = av.w;
        Bs[lcol + 0][lrow] = bv.x; Bs[lcol + 1][lrow] = bv.y;
        Bs[lcol + 2][lrow] = bv.z; Bs[lcol + 3][lrow] = bv.w;
        __syncthreads();
        if (k0 + 8 < K) {                       // prefetch next K-slab
            av = *(const float4*)(Aptr + k0 + 8);
            bv = *(const float4*)(Bptr + k0 + 8);
        }
        #pragma unroll
        for (int kk = 0; kk < 8; kk++) {
            float ar[8], br[8];
            *(float4*)&ar[0] = *(const float4*)&As[kk][ty * 8];
            *(float4*)&ar[4] = *(const float4*)&As[kk][ty * 8 + 4];
            *(float4*)&br[0] = *(const float4*)&Bs[kk][tx * 8];
            *(float4*)&br[4] = *(const float4*)&Bs[kk][tx * 8 + 4];
            #pragma unroll
            for (int i = 0; i < 8; i++)
                #pragma unroll
                for (int j = 0; j < 8; j++)
                    acc[i][j] = fmaf(ar[i], br[j], acc[i][j]);
        }
    }
    // epilogue: logits = 3*acc + 3*b1[n] + class_offsets[n]
    float cb[8];
    #pragma unroll
    for (int j = 0; j < 8; j++) {
        int n = n0 + tx * 8 + j;
        cb[j] = 3.0f * __ldg(&b1[n]) + __ldg(&coff[n]);
    }
    #pragma unroll
    for (int i = 0; i < 8; i++) {
        int m = m0 + ty * 8 + i;
        float* orow = g_logits + (size_t)m * C_ + n0 + tx * 8;
        float4 v0, v1;
        v0.x = 3.0f * acc[i][0] + cb[0]; v0.y = 3.0f * acc[i][1] + cb[1];
        v0.z = 3.0f * acc[i][2] + cb[2]; v0.w = 3.0f * acc[i][3] + cb[3];
        v1.x = 3.0f * acc[i][4] + cb[4]; v1.y = 3.0f * acc[i][5] + cb[5];
        v1.z = 3.0f * acc[i][6] + cb[6]; v1.w = 3.0f * acc[i][7] + cb[7];
        *(float4*)&orow[0] = v0;
        *(float4*)&orow[4] = v1;
    }
}

// ---------------- warp helpers ----------------
__device__ __forceinline__ int warp_argmax(float z, int lane) {
    float bv = z; int bi = lane;
    #pragma unroll
    for (int off = 16; off; off >>= 1) {
        float ov = __shfl_xor_sync(0xffffffffu, bv, off);
        int   oi = __shfl_xor_sync(0xffffffffu, bi, off);
        if (ov > bv || (ov == bv && oi < bi)) { bv = ov; bi = oi; }
    }
    return bi;  // identical in all lanes (ties -> lowest index, like jnp.argmax)
}

// ---------------- kernel 2: fused softmax/sample/gather/LN per token -------
__global__ void __launch_bounds__(256)
fused_k(const float* __restrict__ g1, const float* __restrict__ g2,
        const float* __restrict__ wI, const float* __restrict__ uI,
        const float* __restrict__ b2, const float* __restrict__ gamma,
        const float* __restrict__ beta,
        float* __restrict__ oSamp, float* __restrict__ oSoft,
        float* __restrict__ oPos,  float* __restrict__ oNeg)
{
    const int t    = blockIdx.x;          // token
    const int tid  = threadIdx.x;
    const int lane = tid & 31;
    const int wid  = tid >> 5;            // 8 warps

    __shared__ float sWi[G_], sWj[G_];
    __shared__ int   sIA[G_], sIB[G_];
    __shared__ float sPos[E_];
    __shared__ float rbuf[18];

    const size_t baseC = (size_t)t * C_;

    // --- phase 1: per-group softmax + two Gumbel argmaxes + sparse sampled ---
    for (int g = wid; g < G_; g += 8) {
        const size_t idx = baseC + g * CG_ + lane;
        float v = g_logits[idx];
        // softmax (max-subtracted)
        float m = v;
        #pragma unroll
        for (int off = 16; off; off >>= 1)
            m = fmaxf(m, __shfl_xor_sync(0xffffffffu, m, off));
        float e = __expf(v - m);
        float s = e;
        #pragma unroll
        for (int off = 16; off; off >>= 1)
            s += __shfl_xor_sync(0xffffffffu, s, off);
        oSoft[idx] = e / s;

        // argmax(logits + gumbel) twice
        int i1 = warp_argmax(v + __ldg(&g1[idx]), lane);
        int i2 = warp_argmax(v + __ldg(&g2[idx]), lane);

        float w = __ldg(&wI[t * G_ + g]);
        float u = __ldg(&uI[t * G_ + g]);
        float cwi, cwj;
        if (u < 1.0f) { cwi = w;    cwj = 1.0f - w; }
        else          { cwi = 1.0f; cwj = 0.0f;     }

        float val = 0.0f;
        if (lane == i1) val += cwi;
        if (lane == i2) val += cwj;
        oSamp[idx] = val;            // forward value of straight-through == hard

        if (lane == 0) {
            sIA[g] = g * CG_ + i1;  sIB[g] = g * CG_ + i2;
            sWi[g] = cwi;           sWj[g] = cwj;
        }
    }
    __syncthreads();

    // --- phase 2: sparse projection  pos_pre[e] = b2[e] + sum_g (wi*W2T[iA] + wj*W2T[iB])[e]
    float s_sum = 0.f, s_sq = 0.f;
    #pragma unroll
    for (int r = 0; r < 2; r++) {
        const int e = tid + r * 256;
        float acc = __ldg(&b2[e]);
        #pragma unroll
        for (int g = 0; g < G_; g++) {
            acc = fmaf(sWi[g], g_W2T[(size_t)sIA[g] * E_ + e], acc);
            acc = fmaf(sWj[g], g_W2T[(size_t)sIB[g] * E_ + e], acc);
        }
        sPos[e] = acc;
        s_sum += acc;
        s_sq  += acc * acc;
    }

    // --- phase 3: LayerNorm reduction over E=512 ---
    #pragma unroll
    for (int off = 16; off; off >>= 1) {
        s_sum += __shfl_xor_sync(0xffffffffu, s_sum, off);
        s_sq  += __shfl_xor_sync(0xffffffffu, s_sq,  off);
    }
    if (lane == 0) { rbuf[wid] = s_sum; rbuf[8 + wid] = s_sq; }
    __syncthreads();
    if (tid == 0) {
        float S = 0.f, S2 = 0.f;
        #pragma unroll
        for (int w = 0; w < 8; w++) { S += rbuf[w]; S2 += rbuf[8 + w]; }
        float mu  = S * (1.0f / E_);
        float var = S2 * (1.0f / E_) - mu * mu;
        rbuf[16] = mu;
        rbuf[17] = rsqrtf(var + LN_EPS);
    }
    __syncthreads();
    const float mu = rbuf[16], inv = rbuf[17];

    const size_t baseE = (size_t)t * E_;
    #pragma unroll
    for (int r = 0; r < 2; r++) {
        const int e = tid + r * 256;
        float y = (sPos[e] - mu) * inv * __ldg(&gamma[e]) + __ldg(&beta[e]);
        oPos[baseE + e] = y;
        oNeg[baseE + e] = y;   // forward of reverse_gradient path == pos
    }
}

// ---------------- launcher ----------------
extern "C" void kernel_launch(void* const* d_in, const int* in_sizes, int n_in,
                              void* d_out, int out_size)
{
    const float* x     = (const float*)d_in[0];
    const float* W1    = (const float*)d_in[1];
    const float* b1    = (const float*)d_in[2];
    const float* coff  = (const float*)d_in[3];
    const float* W2    = (const float*)d_in[4];
    const float* b2    = (const float*)d_in[5];
    const float* gam   = (const float*)d_in[6];
    const float* bet   = (const float*)d_in[7];
    const float* g1    = (const float*)d_in[8];
    const float* g2    = (const float*)d_in[9];
    const float* wI    = (const float*)d_in[10];
    const float* uI    = (const float*)d_in[11];

    float* out     = (float*)d_out;
    float* o_samp  = out;                                   // [TOK, C]
    float* o_soft  = out + (size_t)TOK_ * C_;               // [TOK, C]
    float* o_pos   = out + (size_t)2 * TOK_ * C_;           // [TOK, E]
    float* o_neg   = o_pos + (size_t)TOK_ * E_;             // [TOK, E]

    transpose_k<<<dim3(C_ / 32, E_ / 32), dim3(32, 32)>>>(W2);
    gemm1_k<<<dim3(C_ / 128, TOK_ / 128), 256>>>(x, W1, b1, coff);
    fused_k<<<TOK_, 256>>>(g1, g2, wI, uI, b2, gam, bet,
                           o_samp, o_soft, o_pos, o_neg);
}

// round 8
// speedup vs baseline: 1.3434x; 1.3434x over previous
#include <cuda_runtime.h>
#include <cuda_bf16.h>
#include <cstdint>

// ---------------- problem constants ----------------
#define S_    2048
#define N_    8
#define E_    512
#define C_    1024
#define G_    32
#define CG_   32
#define TOK_  (S_ * N_)          // 16384 tokens
#define LN_EPS 1e-5f

// GEMM tiling (mma.sync path — tcgen05 unavailable: toolchain targets sm_103 baseline)
#define BM 128
#define BN 128
#define BK 32
#define NCHUNK 48                 // 3 split segments x (512/32)
#define ASTRIDE 40                // smem row stride in bf16 elems (80 B)

// refinement trigger: approx-logit error bound ~1e-4; 30x headroom
#define REFINE_THR 3e-3f

// ---------------- scratch (device globals) --------
__device__ float g_logits[(size_t)TOK_ * C_];          // 64 MB
__device__ float g_W2T[(size_t)C_ * E_];               // 2 MB
__device__ __nv_bfloat16 g_Ahi[(size_t)TOK_ * E_];     // 16 MB
__device__ __nv_bfloat16 g_Alo[(size_t)TOK_ * E_];     // 16 MB
__device__ __nv_bfloat16 g_Bhi[(size_t)C_ * E_];       // 1 MB
__device__ __nv_bfloat16 g_Blo[(size_t)C_ * E_];       // 1 MB

// ---------------- helpers ----------------
__device__ __forceinline__ uint32_t smem_u32(const void* p) {
    uint32_t a;
    asm("{ .reg .u64 t; cvta.to.shared.u64 t, %1; cvt.u32.u64 %0, t; }"
        : "=r"(a) : "l"(p));
    return a;
}
__device__ __forceinline__ void cp16(uint32_t saddr, const void* gptr) {
    asm volatile("cp.async.cg.shared.global [%0], [%1], 16;"
                 :: "r"(saddr), "l"(gptr) : "memory");
}
__device__ __forceinline__ void ldm_x4(uint32_t* r, uint32_t addr) {
    asm volatile("ldmatrix.sync.aligned.m8n8.x4.shared.b16 {%0,%1,%2,%3}, [%4];"
                 : "=r"(r[0]), "=r"(r[1]), "=r"(r[2]), "=r"(r[3]) : "r"(addr));
}
__device__ __forceinline__ void mma16816(float* c, const uint32_t* a, const uint32_t* b) {
    asm volatile(
        "mma.sync.aligned.m16n8k16.row.col.f32.bf16.bf16.f32 "
        "{%0,%1,%2,%3}, {%4,%5,%6,%7}, {%8,%9}, {%0,%1,%2,%3};"
        : "+f"(c[0]), "+f"(c[1]), "+f"(c[2]), "+f"(c[3])
        : "r"(a[0]), "r"(a[1]), "r"(a[2]), "r"(a[3]), "r"(b[0]), "r"(b[1]));
}

// ---------------- kernel 0: transpose W2 (E x C) -> W2T (C x E) -----------
__global__ void transpose_k(const float* __restrict__ W2) {
    __shared__ float tile[32][33];
    int c = blockIdx.x * 32 + threadIdx.x;
    int e = blockIdx.y * 32 + threadIdx.y;
    tile[threadIdx.y][threadIdx.x] = W2[(size_t)e * C_ + c];
    __syncthreads();
    int e2 = blockIdx.y * 32 + threadIdx.x;
    int c2 = blockIdx.x * 32 + threadIdx.y;
    g_W2T[(size_t)c2 * E_ + e2] = tile[threadIdx.x][threadIdx.y];
}

// ---------------- kernel 0b: fp32 -> (bf16 hi, bf16 lo) splits -----------
__global__ void split_x_k(const float* __restrict__ in) {
    int i = blockIdx.x * 256 + threadIdx.x;
    if (i < TOK_ * E_) {
        float v = in[i];
        __nv_bfloat16 h = __float2bfloat16(v);
        g_Ahi[i] = h;
        g_Alo[i] = __float2bfloat16(v - __bfloat162float(h));
    }
}
__global__ void split_w_k(const float* __restrict__ in) {
    int i = blockIdx.x * 256 + threadIdx.x;
    if (i < C_ * E_) {
        float v = in[i];
        __nv_bfloat16 h = __float2bfloat16(v);
        g_Bhi[i] = h;
        g_Blo[i] = __float2bfloat16(v - __bfloat162float(h));
    }
}

// ---------------- kernel 1: bf16 split-GEMM via mma.sync -----------------
// logits[m][n] = 3*( x[m,:].W1[n,:] + b1[n] ) + coff[n]
// effective K = 1536: seg0 Ahi.Bhi, seg1 Ahi.Blo, seg2 Alo.Bhi
__global__ void __launch_bounds__(256, 2)
gemm_mma(const float* __restrict__ b1, const float* __restrict__ coff)
{
    __shared__ __align__(16) __nv_bfloat16 sA[2][BM * ASTRIDE];
    __shared__ __align__(16) __nv_bfloat16 sB[2][BN * ASTRIDE];

    const int tid  = threadIdx.x;
    const int lane = tid & 31;
    const int wid  = tid >> 5;
    const int wm   = (wid & 3) * 32;   // warp m-offset in tile
    const int wn   = (wid >> 2) * 64;  // warp n-offset in tile
    const int m0   = blockIdx.y * BM;
    const int n0   = blockIdx.x * BN;

    const uint32_t aBase[2] = { smem_u32(&sA[0][0]), smem_u32(&sA[1][0]) };
    const uint32_t bBase[2] = { smem_u32(&sB[0][0]), smem_u32(&sB[1][0]) };

    const int lrow0 = tid >> 2,         lcg0 = (tid & 3);
    const int lrow1 = (tid + 256) >> 2, lcg1 = ((tid + 256) & 3);

    auto issue_loads = [&](int kc) {
        const int b   = kc & 1;
        const int seg = kc >> 4;
        const __nv_bfloat16* Asrc = (seg == 2) ? g_Alo : g_Ahi;
        const __nv_bfloat16* Bsrc = (seg == 1) ? g_Blo : g_Bhi;
        const int kcol = (kc & 15) * BK;
        cp16(aBase[b] + (uint32_t)(lrow0 * ASTRIDE + lcg0 * 8) * 2,
             Asrc + (size_t)(m0 + lrow0) * E_ + kcol + lcg0 * 8);
        cp16(aBase[b] + (uint32_t)(lrow1 * ASTRIDE + lcg1 * 8) * 2,
             Asrc + (size_t)(m0 + lrow1) * E_ + kcol + lcg1 * 8);
        cp16(bBase[b] + (uint32_t)(lrow0 * ASTRIDE + lcg0 * 8) * 2,
             Bsrc + (size_t)(n0 + lrow0) * E_ + kcol + lcg0 * 8);
        cp16(bBase[b] + (uint32_t)(lrow1 * ASTRIDE + lcg1 * 8) * 2,
             Bsrc + (size_t)(n0 + lrow1) * E_ + kcol + lcg1 * 8);
        asm volatile("cp.async.commit_group;" ::: "memory");
    };

    float acc[2][8][4];
    #pragma unroll
    for (int i = 0; i < 2; i++)
        #pragma unroll
        for (int j = 0; j < 8; j++)
            #pragma unroll
            for (int r = 0; r < 4; r++) acc[i][j][r] = 0.0f;

    issue_loads(0);

    for (int kc = 0; kc < NCHUNK; kc++) {
        const int b = kc & 1;
        if (kc + 1 < NCHUNK) {
            issue_loads(kc + 1);
            asm volatile("cp.async.wait_group 1;" ::: "memory");
        } else {
            asm volatile("cp.async.wait_group 0;" ::: "memory");
        }
        __syncthreads();

        #pragma unroll
        for (int ks = 0; ks < 2; ks++) {
            uint32_t afr[2][4];
            #pragma unroll
            for (int i = 0; i < 2; i++) {
                int row  = wm + i * 16 + (lane & 7) + ((lane >> 3) & 1) * 8;
                int half = lane >> 4;
                ldm_x4(afr[i], aBase[b] + row * (ASTRIDE * 2) + ks * 32 + half * 16);
            }
            uint32_t bfr[8][2];
            #pragma unroll
            for (int bj = 0; bj < 4; bj++) {
                int row  = wn + bj * 16 + (lane & 7) + (lane >> 4) * 8;
                int half = (lane >> 3) & 1;
                uint32_t q[4];
                ldm_x4(q, bBase[b] + row * (ASTRIDE * 2) + ks * 32 + half * 16);
                bfr[bj * 2][0] = q[0];     bfr[bj * 2][1] = q[1];
                bfr[bj * 2 + 1][0] = q[2]; bfr[bj * 2 + 1][1] = q[3];
            }
            #pragma unroll
            for (int i = 0; i < 2; i++)
                #pragma unroll
                for (int j = 0; j < 8; j++)
                    mma16816(acc[i][j], afr[i], bfr[j]);
        }
        __syncthreads();
    }

    // epilogue: logits = 3*acc + (3*b1 + coff), direct float2 stores
    const int gp   = lane >> 2;
    const int tid4 = lane & 3;
    #pragma unroll
    for (int j = 0; j < 8; j++) {
        const int n = n0 + wn + j * 8 + tid4 * 2;
        const float c0 = fmaf(3.0f, __ldg(&b1[n + 0]), __ldg(&coff[n + 0]));
        const float c1 = fmaf(3.0f, __ldg(&b1[n + 1]), __ldg(&coff[n + 1]));
        #pragma unroll
        for (int i = 0; i < 2; i++) {
            const int mrow = m0 + wm + i * 16 + gp;
            float2 v0, v1;
            v0.x = fmaf(3.0f, acc[i][j][0], c0);
            v0.y = fmaf(3.0f, acc[i][j][1], c1);
            v1.x = fmaf(3.0f, acc[i][j][2], c0);
            v1.y = fmaf(3.0f, acc[i][j][3], c1);
            *(float2*)&g_logits[(size_t)mrow * C_ + n]       = v0;
            *(float2*)&g_logits[(size_t)(mrow + 8) * C_ + n] = v1;
        }
    }
}

// ---------------- warp helpers ----------------
__device__ __forceinline__ int warp_argmax(float z, int lane) {
    float bv = z; int bi = lane;
    #pragma unroll
    for (int off = 16; off; off >>= 1) {
        float ov = __shfl_xor_sync(0xffffffffu, bv, off);
        int   oi = __shfl_xor_sync(0xffffffffu, bi, off);
        if (ov > bv || (ov == bv && oi < bi)) { bv = ov; bi = oi; }
    }
    return bi;
}
__device__ __forceinline__ int warp_argmax_m(float z, int lane, float* mar) {
    float bv = z; int bi = lane;
    #pragma unroll
    for (int off = 16; off; off >>= 1) {
        float ov = __shfl_xor_sync(0xffffffffu, bv, off);
        int   oi = __shfl_xor_sync(0xffffffffu, bi, off);
        if (ov > bv || (ov == bv && oi < bi)) { bv = ov; bi = oi; }
    }
    float z2 = (lane == bi) ? -3.4e38f : z;
    #pragma unroll
    for (int off = 16; off; off >>= 1)
        z2 = fmaxf(z2, __shfl_xor_sync(0xffffffffu, z2, off));
    *mar = bv - z2;
    return bi;
}

// ---------------- kernel 2: fused softmax/sample/gather/LN per token -------
__global__ void __launch_bounds__(256)
fused_k(const float* __restrict__ g1, const float* __restrict__ g2,
        const float* __restrict__ wI, const float* __restrict__ uI,
        const float* __restrict__ b2, const float* __restrict__ gamma,
        const float* __restrict__ beta,
        const float* __restrict__ x,  const float* __restrict__ W1,
        const float* __restrict__ b1, const float* __restrict__ coff,
        float* __restrict__ oSamp, float* __restrict__ oSoft,
        float* __restrict__ oPos,  float* __restrict__ oNeg)
{
    const int t    = blockIdx.x;
    const int tid  = threadIdx.x;
    const int lane = tid & 31;
    const int wid  = tid >> 5;

    __shared__ float sWi[G_], sWj[G_];
    __shared__ int   sIA[G_], sIB[G_];
    __shared__ float sPos[E_];
    __shared__ float rbuf[18];

    const size_t baseC = (size_t)t * C_;

    for (int g = wid; g < G_; g += 8) {
        const size_t idx = baseC + g * CG_ + lane;
        float v = g_logits[idx];
        float m = v;
        #pragma unroll
        for (int off = 16; off; off >>= 1)
            m = fmaxf(m, __shfl_xor_sync(0xffffffffu, m, off));
        float e = __expf(v - m);
        float s = e;
        #pragma unroll
        for (int off = 16; off; off >>= 1)
            s += __shfl_xor_sync(0xffffffffu, s, off);
        oSoft[idx] = e / s;

        float gu1 = __ldg(&g1[idx]);
        float gu2 = __ldg(&g2[idx]);
        float m1, m2;
        int i1 = warp_argmax_m(v + gu1, lane, &m1);
        int i2 = warp_argmax_m(v + gu2, lane, &m2);

        // Near-tie refinement: recompute the group's logits with the EXACT
        // sequential-fmaf fp32 chain (k ascending) that the proven-correct
        // fp32 GEMM used — bit-identical inputs + op order => bit-identical
        // logits => identical argmax outcomes on near-tie margins.
        if (m1 < REFINE_THR || m2 < REFINE_THR) {
            const int cls = g * CG_ + lane;
            const float4* x4 = (const float4*)(x + (size_t)t * E_);
            const float4* w4 = (const float4*)(W1 + (size_t)cls * E_);
            float acc = 0.f;
            #pragma unroll 4
            for (int k = 0; k < E_ / 4; k++) {
                float4 a = __ldg(&x4[k]);
                float4 b = __ldg(&w4[k]);
                acc = fmaf(a.x, b.x, acc);
                acc = fmaf(a.y, b.y, acc);
                acc = fmaf(a.z, b.z, acc);
                acc = fmaf(a.w, b.w, acc);
            }
            float cb = fmaf(3.0f, __ldg(&b1[cls]), __ldg(&coff[cls]));
            float vr = fmaf(3.0f, acc, cb);
            i1 = warp_argmax(vr + gu1, lane);
            i2 = warp_argmax(vr + gu2, lane);
        }

        float w = __ldg(&wI[t * G_ + g]);
        float u = __ldg(&uI[t * G_ + g]);
        float cwi, cwj;
        if (u < 1.0f) { cwi = w;    cwj = 1.0f - w; }
        else          { cwi = 1.0f; cwj = 0.0f;     }

        float val = 0.0f;
        if (lane == i1) val += cwi;
        if (lane == i2) val += cwj;
        oSamp[idx] = val;

        if (lane == 0) {
            sIA[g] = g * CG_ + i1;  sIB[g] = g * CG_ + i2;
            sWi[g] = cwi;           sWj[g] = cwj;
        }
    }
    __syncthreads();

    float s_sum = 0.f, s_sq = 0.f;
    #pragma unroll
    for (int r = 0; r < 2; r++) {
        const int e = tid + r * 256;
        float acc = __ldg(&b2[e]);
        #pragma unroll
        for (int g = 0; g < G_; g++) {
            acc = fmaf(sWi[g], g_W2T[(size_t)sIA[g] * E_ + e], acc);
            acc = fmaf(sWj[g], g_W2T[(size_t)sIB[g] * E_ + e], acc);
        }
        sPos[e] = acc;
        s_sum += acc;
        s_sq  += acc * acc;
    }

    #pragma unroll
    for (int off = 16; off; off >>= 1) {
        s_sum += __shfl_xor_sync(0xffffffffu, s_sum, off);
        s_sq  += __shfl_xor_sync(0xffffffffu, s_sq,  off);
    }
    if (lane == 0) { rbuf[wid] = s_sum; rbuf[8 + wid] = s_sq; }
    __syncthreads();
    if (tid == 0) {
        float S = 0.f, S2 = 0.f;
        #pragma unroll
        for (int w = 0; w < 8; w++) { S += rbuf[w]; S2 += rbuf[8 + w]; }
        float mu  = S * (1.0f / E_);
        float var = S2 * (1.0f / E_) - mu * mu;
        rbuf[16] = mu;
        rbuf[17] = rsqrtf(var + LN_EPS);
    }
    __syncthreads();
    const float mu = rbuf[16], inv = rbuf[17];

    const size_t baseE = (size_t)t * E_;
    #pragma unroll
    for (int r = 0; r < 2; r++) {
        const int e = tid + r * 256;
        float y = (sPos[e] - mu) * inv * __ldg(&gamma[e]) + __ldg(&beta[e]);
        oPos[baseE + e] = y;
        oNeg[baseE + e] = y;
    }
}

// ---------------- launcher (pure kernel launches; graph-capture safe) ------
extern "C" void kernel_launch(void* const* d_in, const int* in_sizes, int n_in,
                              void* d_out, int out_size)
{
    const float* x     = (const float*)d_in[0];
    const float* W1    = (const float*)d_in[1];
    const float* b1    = (const float*)d_in[2];
    const float* coff  = (const float*)d_in[3];
    const float* W2    = (const float*)d_in[4];
    const float* b2    = (const float*)d_in[5];
    const float* gam   = (const float*)d_in[6];
    const float* bet   = (const float*)d_in[7];
    const float* g1    = (const float*)d_in[8];
    const float* g2    = (const float*)d_in[9];
    const float* wI    = (const float*)d_in[10];
    const float* uI    = (const float*)d_in[11];

    float* out     = (float*)d_out;
    float* o_samp  = out;
    float* o_soft  = out + (size_t)TOK_ * C_;
    float* o_pos   = out + (size_t)2 * TOK_ * C_;
    float* o_neg   = o_pos + (size_t)TOK_ * E_;

    transpose_k<<<dim3(C_ / 32, E_ / 32), dim3(32, 32)>>>(W2);
    split_x_k<<<(TOK_ * E_ + 255) / 256, 256>>>(x);
    split_w_k<<<(C_ * E_   + 255) / 256, 256>>>(W1);
    gemm_mma<<<dim3(C_ / BN, TOK_ / BM), 256>>>(b1, coff);
    fused_k<<<TOK_, 256>>>(g1, g2, wI, uI, b2, gam, bet,
                           x, W1, b1, coff,
                           o_samp, o_soft, o_pos, o_neg);
}

// round 9
// speedup vs baseline: 1.3941x; 1.0377x over previous
#include <cuda_runtime.h>
#include <cuda_bf16.h>
#include <cstdint>

// ---------------- problem constants ----------------
#define S_    2048
#define N_    8
#define E_    512
#define C_    1024
#define G_    32
#define CG_   32
#define TOK_  (S_ * N_)          // 16384 tokens
#define LN_EPS 1e-5f

// GEMM tiling (mma.sync path — tcgen05 unavailable: toolchain targets sm_103 baseline)
#define BM 128
#define BN 128
#define BK 32
#define NCHUNK 48                 // 3 split segments x (512/32)
#define ASTRIDE 40                // smem row stride in bf16 elems (80 B)

// refinement trigger: approx-logit error bound ~1e-4; 30x headroom
#define REFINE_THR 3e-3f

// ---------------- scratch (device globals) --------
__device__ float g_logits[(size_t)TOK_ * C_];          // 64 MB
__device__ float g_W2T[(size_t)C_ * E_];               // 2 MB
__device__ __nv_bfloat16 g_Ahi[(size_t)TOK_ * E_];     // 16 MB
__device__ __nv_bfloat16 g_Alo[(size_t)TOK_ * E_];     // 16 MB
__device__ __nv_bfloat16 g_Bhi[(size_t)C_ * E_];       // 1 MB
__device__ __nv_bfloat16 g_Blo[(size_t)C_ * E_];       // 1 MB

// ---------------- helpers ----------------
__device__ __forceinline__ uint32_t smem_u32(const void* p) {
    uint32_t a;
    asm("{ .reg .u64 t; cvta.to.shared.u64 t, %1; cvt.u32.u64 %0, t; }"
        : "=r"(a) : "l"(p));
    return a;
}
__device__ __forceinline__ void cp16(uint32_t saddr, const void* gptr) {
    asm volatile("cp.async.cg.shared.global [%0], [%1], 16;"
                 :: "r"(saddr), "l"(gptr) : "memory");
}
__device__ __forceinline__ void ldm_x4(uint32_t* r, uint32_t addr) {
    asm volatile("ldmatrix.sync.aligned.m8n8.x4.shared.b16 {%0,%1,%2,%3}, [%4];"
                 : "=r"(r[0]), "=r"(r[1]), "=r"(r[2]), "=r"(r[3]) : "r"(addr));
}
__device__ __forceinline__ void mma16816(float* c, const uint32_t* a, const uint32_t* b) {
    asm volatile(
        "mma.sync.aligned.m16n8k16.row.col.f32.bf16.bf16.f32 "
        "{%0,%1,%2,%3}, {%4,%5,%6,%7}, {%8,%9}, {%0,%1,%2,%3};"
        : "+f"(c[0]), "+f"(c[1]), "+f"(c[2]), "+f"(c[3])
        : "r"(a[0]), "r"(a[1]), "r"(a[2]), "r"(a[3]), "r"(b[0]), "r"(b[1]));
}

// ---------------- kernel 0: transpose W2 (E x C) -> W2T (C x E) -----------
__global__ void transpose_k(const float* __restrict__ W2) {
    __shared__ float tile[32][33];
    int c = blockIdx.x * 32 + threadIdx.x;
    int e = blockIdx.y * 32 + threadIdx.y;
    tile[threadIdx.y][threadIdx.x] = W2[(size_t)e * C_ + c];
    __syncthreads();
    int e2 = blockIdx.y * 32 + threadIdx.x;
    int c2 = blockIdx.x * 32 + threadIdx.y;
    g_W2T[(size_t)c2 * E_ + e2] = tile[threadIdx.x][threadIdx.y];
}

// ---------------- kernel 0b: fp32 -> (bf16 hi, bf16 lo) splits (float4) ---
__device__ __forceinline__ void split4_store(__nv_bfloat16* hi, __nv_bfloat16* lo,
                                             int i, float4 v) {
    __nv_bfloat16 h0 = __float2bfloat16(v.x), h1 = __float2bfloat16(v.y);
    __nv_bfloat16 h2 = __float2bfloat16(v.z), h3 = __float2bfloat16(v.w);
    __nv_bfloat162 hi01, hi23, lo01, lo23;
    hi01.x = h0; hi01.y = h1; hi23.x = h2; hi23.y = h3;
    lo01.x = __float2bfloat16(v.x - __bfloat162float(h0));
    lo01.y = __float2bfloat16(v.y - __bfloat162float(h1));
    lo23.x = __float2bfloat16(v.z - __bfloat162float(h2));
    lo23.y = __float2bfloat16(v.w - __bfloat162float(h3));
    ((__nv_bfloat162*)hi)[i * 2]     = hi01;
    ((__nv_bfloat162*)hi)[i * 2 + 1] = hi23;
    ((__nv_bfloat162*)lo)[i * 2]     = lo01;
    ((__nv_bfloat162*)lo)[i * 2 + 1] = lo23;
}
__global__ void split_x_k(const float* __restrict__ in) {
    int i = blockIdx.x * 256 + threadIdx.x;
    if (i < TOK_ * E_ / 4)
        split4_store(g_Ahi, g_Alo, i, ((const float4*)in)[i]);
}
__global__ void split_w_k(const float* __restrict__ in) {
    int i = blockIdx.x * 256 + threadIdx.x;
    if (i < C_ * E_ / 4)
        split4_store(g_Bhi, g_Blo, i, ((const float4*)in)[i]);
}

// ---------------- kernel 1: bf16 split-GEMM via mma.sync (unchanged) ------
__global__ void __launch_bounds__(256, 2)
gemm_mma(const float* __restrict__ b1, const float* __restrict__ coff)
{
    __shared__ __align__(16) __nv_bfloat16 sA[2][BM * ASTRIDE];
    __shared__ __align__(16) __nv_bfloat16 sB[2][BN * ASTRIDE];

    const int tid  = threadIdx.x;
    const int lane = tid & 31;
    const int wid  = tid >> 5;
    const int wm   = (wid & 3) * 32;
    const int wn   = (wid >> 2) * 64;
    const int m0   = blockIdx.y * BM;
    const int n0   = blockIdx.x * BN;

    const uint32_t aBase[2] = { smem_u32(&sA[0][0]), smem_u32(&sA[1][0]) };
    const uint32_t bBase[2] = { smem_u32(&sB[0][0]), smem_u32(&sB[1][0]) };

    const int lrow0 = tid >> 2,         lcg0 = (tid & 3);
    const int lrow1 = (tid + 256) >> 2, lcg1 = ((tid + 256) & 3);

    auto issue_loads = [&](int kc) {
        const int b   = kc & 1;
        const int seg = kc >> 4;
        const __nv_bfloat16* Asrc = (seg == 2) ? g_Alo : g_Ahi;
        const __nv_bfloat16* Bsrc = (seg == 1) ? g_Blo : g_Bhi;
        const int kcol = (kc & 15) * BK;
        cp16(aBase[b] + (uint32_t)(lrow0 * ASTRIDE + lcg0 * 8) * 2,
             Asrc + (size_t)(m0 + lrow0) * E_ + kcol + lcg0 * 8);
        cp16(aBase[b] + (uint32_t)(lrow1 * ASTRIDE + lcg1 * 8) * 2,
             Asrc + (size_t)(m0 + lrow1) * E_ + kcol + lcg1 * 8);
        cp16(bBase[b] + (uint32_t)(lrow0 * ASTRIDE + lcg0 * 8) * 2,
             Bsrc + (size_t)(n0 + lrow0) * E_ + kcol + lcg0 * 8);
        cp16(bBase[b] + (uint32_t)(lrow1 * ASTRIDE + lcg1 * 8) * 2,
             Bsrc + (size_t)(n0 + lrow1) * E_ + kcol + lcg1 * 8);
        asm volatile("cp.async.commit_group;" ::: "memory");
    };

    float acc[2][8][4];
    #pragma unroll
    for (int i = 0; i < 2; i++)
        #pragma unroll
        for (int j = 0; j < 8; j++)
            #pragma unroll
            for (int r = 0; r < 4; r++) acc[i][j][r] = 0.0f;

    issue_loads(0);

    for (int kc = 0; kc < NCHUNK; kc++) {
        const int b = kc & 1;
        if (kc + 1 < NCHUNK) {
            issue_loads(kc + 1);
            asm volatile("cp.async.wait_group 1;" ::: "memory");
        } else {
            asm volatile("cp.async.wait_group 0;" ::: "memory");
        }
        __syncthreads();

        #pragma unroll
        for (int ks = 0; ks < 2; ks++) {
            uint32_t afr[2][4];
            #pragma unroll
            for (int i = 0; i < 2; i++) {
                int row  = wm + i * 16 + (lane & 7) + ((lane >> 3) & 1) * 8;
                int half = lane >> 4;
                ldm_x4(afr[i], aBase[b] + row * (ASTRIDE * 2) + ks * 32 + half * 16);
            }
            uint32_t bfr[8][2];
            #pragma unroll
            for (int bj = 0; bj < 4; bj++) {
                int row  = wn + bj * 16 + (lane & 7) + (lane >> 4) * 8;
                int half = (lane >> 3) & 1;
                uint32_t q[4];
                ldm_x4(q, bBase[b] + row * (ASTRIDE * 2) + ks * 32 + half * 16);
                bfr[bj * 2][0] = q[0];     bfr[bj * 2][1] = q[1];
                bfr[bj * 2 + 1][0] = q[2]; bfr[bj * 2 + 1][1] = q[3];
            }
            #pragma unroll
            for (int i = 0; i < 2; i++)
                #pragma unroll
                for (int j = 0; j < 8; j++)
                    mma16816(acc[i][j], afr[i], bfr[j]);
        }
        __syncthreads();
    }

    const int gp   = lane >> 2;
    const int tid4 = lane & 3;
    #pragma unroll
    for (int j = 0; j < 8; j++) {
        const int n = n0 + wn + j * 8 + tid4 * 2;
        const float c0 = fmaf(3.0f, __ldg(&b1[n + 0]), __ldg(&coff[n + 0]));
        const float c1 = fmaf(3.0f, __ldg(&b1[n + 1]), __ldg(&coff[n + 1]));
        #pragma unroll
        for (int i = 0; i < 2; i++) {
            const int mrow = m0 + wm + i * 16 + gp;
            float2 v0, v1;
            v0.x = fmaf(3.0f, acc[i][j][0], c0);
            v0.y = fmaf(3.0f, acc[i][j][1], c1);
            v1.x = fmaf(3.0f, acc[i][j][2], c0);
            v1.y = fmaf(3.0f, acc[i][j][3], c1);
            *(float2*)&g_logits[(size_t)mrow * C_ + n]       = v0;
            *(float2*)&g_logits[(size_t)(mrow + 8) * C_ + n] = v1;
        }
    }
}

// ---------------- warp helpers ----------------
__device__ __forceinline__ int warp_argmax(float z, int lane) {
    float bv = z; int bi = lane;
    #pragma unroll
    for (int off = 16; off; off >>= 1) {
        float ov = __shfl_xor_sync(0xffffffffu, bv, off);
        int   oi = __shfl_xor_sync(0xffffffffu, bi, off);
        if (ov > bv || (ov == bv && oi < bi)) { bv = ov; bi = oi; }
    }
    return bi;
}
__device__ __forceinline__ int warp_argmax_m(float z, int lane, float* mar) {
    float bv = z; int bi = lane;
    #pragma unroll
    for (int off = 16; off; off >>= 1) {
        float ov = __shfl_xor_sync(0xffffffffu, bv, off);
        int   oi = __shfl_xor_sync(0xffffffffu, bi, off);
        if (ov > bv || (ov == bv && oi < bi)) { bv = ov; bi = oi; }
    }
    float z2 = (lane == bi) ? -3.4e38f : z;
    #pragma unroll
    for (int off = 16; off; off >>= 1)
        z2 = fmaxf(z2, __shfl_xor_sync(0xffffffffu, z2, off));
    *mar = bv - z2;
    return bi;
}

// ---------------- kernel 2: fused softmax/sample/gather/LN per token -------
__global__ void __launch_bounds__(256)
fused_k(const float* __restrict__ g1, const float* __restrict__ g2,
        const float* __restrict__ wI, const float* __restrict__ uI,
        const float* __restrict__ b2, const float* __restrict__ gamma,
        const float* __restrict__ beta,
        const float* __restrict__ x,  const float* __restrict__ W1,
        const float* __restrict__ b1, const float* __restrict__ coff,
        float* __restrict__ oSamp, float* __restrict__ oSoft,
        float* __restrict__ oPos,  float* __restrict__ oNeg)
{
    const int t    = blockIdx.x;
    const int tid  = threadIdx.x;
    const int lane = tid & 31;
    const int wid  = tid >> 5;

    __shared__ float sWt[2 * G_];     // [0:32) wi, [32:64) wj
    __shared__ int   sRow[2 * G_];    // [0:32) iA, [32:64) iB
    __shared__ float rbuf[18];

    const size_t baseC = (size_t)t * C_;

    // --- phase 1: per-group softmax + two Gumbel argmaxes + sparse sampled ---
    for (int g = wid; g < G_; g += 8) {
        const size_t idx = baseC + g * CG_ + lane;
        float v = g_logits[idx];
        float m = v;
        #pragma unroll
        for (int off = 16; off; off >>= 1)
            m = fmaxf(m, __shfl_xor_sync(0xffffffffu, m, off));
        float e = __expf(v - m);
        float s = e;
        #pragma unroll
        for (int off = 16; off; off >>= 1)
            s += __shfl_xor_sync(0xffffffffu, s, off);
        oSoft[idx] = e / s;

        float gu1 = __ldg(&g1[idx]);
        float gu2 = __ldg(&g2[idx]);
        float m1, m2;
        int i1 = warp_argmax_m(v + gu1, lane, &m1);
        int i2 = warp_argmax_m(v + gu2, lane, &m2);

        // Near-tie refinement: exact sequential-fmaf fp32 chain (k ascending),
        // bit-identical to the proven fp32 reference numerics.
        if (m1 < REFINE_THR || m2 < REFINE_THR) {
            const int cls = g * CG_ + lane;
            const float4* x4 = (const float4*)(x + (size_t)t * E_);
            const float4* w4 = (const float4*)(W1 + (size_t)cls * E_);
            float acc = 0.f;
            #pragma unroll 4
            for (int k = 0; k < E_ / 4; k++) {
                float4 a = __ldg(&x4[k]);
                float4 b = __ldg(&w4[k]);
                acc = fmaf(a.x, b.x, acc);
                acc = fmaf(a.y, b.y, acc);
                acc = fmaf(a.z, b.z, acc);
                acc = fmaf(a.w, b.w, acc);
            }
            float cb = fmaf(3.0f, __ldg(&b1[cls]), __ldg(&coff[cls]));
            float vr = fmaf(3.0f, acc, cb);
            i1 = warp_argmax(vr + gu1, lane);
            i2 = warp_argmax(vr + gu2, lane);
        }

        float w = __ldg(&wI[t * G_ + g]);
        float u = __ldg(&uI[t * G_ + g]);
        float cwi, cwj;
        if (u < 1.0f) { cwi = w;    cwj = 1.0f - w; }
        else          { cwi = 1.0f; cwj = 0.0f;     }

        float val = 0.0f;
        if (lane == i1) val += cwi;
        if (lane == i2) val += cwj;
        oSamp[idx] = val;

        if (lane == 0) {
            sRow[g]      = g * CG_ + i1;  sWt[g]      = cwi;
            sRow[G_ + g] = g * CG_ + i2;  sWt[G_ + g] = cwj;
        }
    }
    __syncthreads();

    // --- phase 2: sparse projection, float2 per thread, 4 independent chains
    const float2* W2T2 = (const float2*)g_W2T;   // row stride 256 float2
    float2 a0 = {0.f, 0.f}, a1 = {0.f, 0.f}, a2 = {0.f, 0.f}, a3 = {0.f, 0.f};
    #pragma unroll
    for (int p = 0; p < 16; p++) {
        int   r0 = sRow[p],       r1 = sRow[p + 16];
        int   r2 = sRow[p + 32],  r3 = sRow[p + 48];
        float w0 = sWt[p],        w1 = sWt[p + 16];
        float w2 = sWt[p + 32],   w3 = sWt[p + 48];
        float2 v0 = __ldg(&W2T2[(size_t)r0 * 256 + tid]);
        float2 v1 = __ldg(&W2T2[(size_t)r1 * 256 + tid]);
        float2 v2 = __ldg(&W2T2[(size_t)r2 * 256 + tid]);
        float2 v3 = __ldg(&W2T2[(size_t)r3 * 256 + tid]);
        a0.x = fmaf(w0, v0.x, a0.x); a0.y = fmaf(w0, v0.y, a0.y);
        a1.x = fmaf(w1, v1.x, a1.x); a1.y = fmaf(w1, v1.y, a1.y);
        a2.x = fmaf(w2, v2.x, a2.x); a2.y = fmaf(w2, v2.y, a2.y);
        a3.x = fmaf(w3, v3.x, a3.x); a3.y = fmaf(w3, v3.y, a3.y);
    }
    float2 bb = __ldg(&((const float2*)b2)[tid]);
    float accx = ((a0.x + a1.x) + (a2.x + a3.x)) + bb.x;
    float accy = ((a0.y + a1.y) + (a2.y + a3.y)) + bb.y;

    // --- phase 3: LayerNorm from registers ---
    float s_sum = accx + accy;
    float s_sq  = accx * accx + accy * accy;
    #pragma unroll
    for (int off = 16; off; off >>= 1) {
        s_sum += __shfl_xor_sync(0xffffffffu, s_sum, off);
        s_sq  += __shfl_xor_sync(0xffffffffu, s_sq,  off);
    }
    if (lane == 0) { rbuf[wid] = s_sum; rbuf[8 + wid] = s_sq; }
    __syncthreads();
    if (tid == 0) {
        float S = 0.f, S2 = 0.f;
        #pragma unroll
        for (int w = 0; w < 8; w++) { S += rbuf[w]; S2 += rbuf[8 + w]; }
        float mu  = S * (1.0f / E_);
        float var = S2 * (1.0f / E_) - mu * mu;
        rbuf[16] = mu;
        rbuf[17] = rsqrtf(var + LN_EPS);
    }
    __syncthreads();
    const float mu = rbuf[16], inv = rbuf[17];

    float2 gm = __ldg(&((const float2*)gamma)[tid]);
    float2 bt = __ldg(&((const float2*)beta)[tid]);
    float2 y;
    y.x = (accx - mu) * inv * gm.x + bt.x;
    y.y = (accy - mu) * inv * gm.y + bt.y;
    const size_t baseE2 = (size_t)t * (E_ / 2);
    ((float2*)oPos)[baseE2 + tid] = y;
    ((float2*)oNeg)[baseE2 + tid] = y;
}

// ---------------- launcher (pure kernel launches; graph-capture safe) ------
extern "C" void kernel_launch(void* const* d_in, const int* in_sizes, int n_in,
                              void* d_out, int out_size)
{
    const float* x     = (const float*)d_in[0];
    const float* W1    = (const float*)d_in[1];
    const float* b1    = (const float*)d_in[2];
    const float* coff  = (const float*)d_in[3];
    const float* W2    = (const float*)d_in[4];
    const float* b2    = (const float*)d_in[5];
    const float* gam   = (const float*)d_in[6];
    const float* bet   = (const float*)d_in[7];
    const float* g1    = (const float*)d_in[8];
    const float* g2    = (const float*)d_in[9];
    const float* wI    = (const float*)d_in[10];
    const float* uI    = (const float*)d_in[11];

    float* out     = (float*)d_out;
    float* o_samp  = out;
    float* o_soft  = out + (size_t)TOK_ * C_;
    float* o_pos   = out + (size_t)2 * TOK_ * C_;
    float* o_neg   = o_pos + (size_t)TOK_ * E_;

    transpose_k<<<dim3(C_ / 32, E_ / 32), dim3(32, 32)>>>(W2);
    split_x_k<<<(TOK_ * E_ / 4 + 255) / 256, 256>>>(x);
    split_w_k<<<(C_ * E_ / 4 + 255) / 256, 256>>>(W1);
    gemm_mma<<<dim3(C_ / BN, TOK_ / BM), 256>>>(b1, coff);
    fused_k<<<TOK_, 256>>>(g1, g2, wI, uI, b2, gam, bet,
                           x, W1, b1, coff,
                           o_samp, o_soft, o_pos, o_neg);
}

// round 10
// speedup vs baseline: 1.4979x; 1.0744x over previous
#include <cuda_runtime.h>
#include <cuda_fp16.h>
#include <cstdint>

// ---------------- problem constants ----------------
#define S_    2048
#define N_    8
#define E_    512
#define C_    1024
#define G_    32
#define CG_   32
#define TOK_  (S_ * N_)          // 16384 tokens
#define LN_EPS 1e-5f

// GEMM tiling (mma.sync path — tcgen05 unavailable: toolchain targets sm_103 baseline)
#define BM 128
#define BN 128
#define BK 32
#define NCHUNK 32                 // 2 fp16 split segments x (512/32)
#define ASTRIDE 40                // smem row stride in fp16 elems (80 B)

// refinement trigger: fp16-2seg logit error bound ~8e-4 max; 5x headroom
#define REFINE_THR 4e-3f

// ---------------- scratch (device globals) --------
__device__ float g_logits[(size_t)TOK_ * C_];          // 64 MB
__device__ float g_W2T[(size_t)C_ * E_];               // 2 MB
__device__ __half g_Ahi[(size_t)TOK_ * E_];            // 16 MB
__device__ __half g_Alo[(size_t)TOK_ * E_];            // 16 MB
__device__ __half g_Bhi[(size_t)C_ * E_];              // 1 MB

// ---------------- helpers ----------------
__device__ __forceinline__ uint32_t smem_u32(const void* p) {
    uint32_t a;
    asm("{ .reg .u64 t; cvta.to.shared.u64 t, %1; cvt.u32.u64 %0, t; }"
        : "=r"(a) : "l"(p));
    return a;
}
__device__ __forceinline__ void cp16(uint32_t saddr, const void* gptr) {
    asm volatile("cp.async.cg.shared.global [%0], [%1], 16;"
                 :: "r"(saddr), "l"(gptr) : "memory");
}
__device__ __forceinline__ void ldm_x4(uint32_t* r, uint32_t addr) {
    asm volatile("ldmatrix.sync.aligned.m8n8.x4.shared.b16 {%0,%1,%2,%3}, [%4];"
                 : "=r"(r[0]), "=r"(r[1]), "=r"(r[2]), "=r"(r[3]) : "r"(addr));
}
__device__ __forceinline__ void mma16816(float* c, const uint32_t* a, const uint32_t* b) {
    asm volatile(
        "mma.sync.aligned.m16n8k16.row.col.f32.f16.f16.f32 "
        "{%0,%1,%2,%3}, {%4,%5,%6,%7}, {%8,%9}, {%0,%1,%2,%3};"
        : "+f"(c[0]), "+f"(c[1]), "+f"(c[2]), "+f"(c[3])
        : "r"(a[0]), "r"(a[1]), "r"(a[2]), "r"(a[3]), "r"(b[0]), "r"(b[1]));
}

// ---------------- kernel 0: transpose W2 (E x C) -> W2T (C x E) -----------
__global__ void transpose_k(const float* __restrict__ W2) {
    __shared__ float tile[32][33];
    int c = blockIdx.x * 32 + threadIdx.x;
    int e = blockIdx.y * 32 + threadIdx.y;
    tile[threadIdx.y][threadIdx.x] = W2[(size_t)e * C_ + c];
    __syncthreads();
    int e2 = blockIdx.y * 32 + threadIdx.x;
    int c2 = blockIdx.x * 32 + threadIdx.y;
    g_W2T[(size_t)c2 * E_ + e2] = tile[threadIdx.x][threadIdx.y];
}

// ---------------- kernel 0b: fp32 -> (fp16 hi, fp16 lo) splits ------------
__global__ void split_x_k(const float* __restrict__ in) {
    int i = blockIdx.x * 256 + threadIdx.x;
    if (i < TOK_ * E_ / 4) {
        float4 v = ((const float4*)in)[i];
        __half h0 = __float2half_rn(v.x), h1 = __float2half_rn(v.y);
        __half h2 = __float2half_rn(v.z), h3 = __float2half_rn(v.w);
        __half2 hi01, hi23, lo01, lo23;
        hi01.x = h0; hi01.y = h1; hi23.x = h2; hi23.y = h3;
        lo01.x = __float2half_rn(v.x - __half2float(h0));
        lo01.y = __float2half_rn(v.y - __half2float(h1));
        lo23.x = __float2half_rn(v.z - __half2float(h2));
        lo23.y = __float2half_rn(v.w - __half2float(h3));
        ((__half2*)g_Ahi)[i * 2]     = hi01;
        ((__half2*)g_Ahi)[i * 2 + 1] = hi23;
        ((__half2*)g_Alo)[i * 2]     = lo01;
        ((__half2*)g_Alo)[i * 2 + 1] = lo23;
    }
}
__global__ void split_w_k(const float* __restrict__ in) {
    int i = blockIdx.x * 256 + threadIdx.x;
    if (i < C_ * E_ / 4) {
        float4 v = ((const float4*)in)[i];
        __half2 hi01, hi23;
        hi01.x = __float2half_rn(v.x); hi01.y = __float2half_rn(v.y);
        hi23.x = __float2half_rn(v.z); hi23.y = __float2half_rn(v.w);
        ((__half2*)g_Bhi)[i * 2]     = hi01;
        ((__half2*)g_Bhi)[i * 2 + 1] = hi23;
    }
}

// ---------------- kernel 1: fp16 split-GEMM via mma.sync ------------------
// logits[m][n] = 3*( x[m,:].W1[n,:] + b1[n] ) + coff[n]
// effective K = 1024: seg0 Ahi.Bhi, seg1 Alo.Bhi   (drops x.W_lo, ~2e-4 rms)
__global__ void __launch_bounds__(256, 2)
gemm_mma(const float* __restrict__ b1, const float* __restrict__ coff)
{
    __shared__ __align__(16) __half sA[2][BM * ASTRIDE];
    __shared__ __align__(16) __half sB[2][BN * ASTRIDE];

    const int tid  = threadIdx.x;
    const int lane = tid & 31;
    const int wid  = tid >> 5;
    const int wm   = (wid & 3) * 32;
    const int wn   = (wid >> 2) * 64;
    const int m0   = blockIdx.y * BM;
    const int n0   = blockIdx.x * BN;

    const uint32_t aBase[2] = { smem_u32(&sA[0][0]), smem_u32(&sA[1][0]) };
    const uint32_t bBase[2] = { smem_u32(&sB[0][0]), smem_u32(&sB[1][0]) };

    const int lrow0 = tid >> 2,         lcg0 = (tid & 3);
    const int lrow1 = (tid + 256) >> 2, lcg1 = ((tid + 256) & 3);

    auto issue_loads = [&](int kc) {
        const int b   = kc & 1;
        const int seg = kc >> 4;
        const __half* Asrc = seg ? g_Alo : g_Ahi;
        const __half* Bsrc = g_Bhi;
        const int kcol = (kc & 15) * BK;
        cp16(aBase[b] + (uint32_t)(lrow0 * ASTRIDE + lcg0 * 8) * 2,
             Asrc + (size_t)(m0 + lrow0) * E_ + kcol + lcg0 * 8);
        cp16(aBase[b] + (uint32_t)(lrow1 * ASTRIDE + lcg1 * 8) * 2,
             Asrc + (size_t)(m0 + lrow1) * E_ + kcol + lcg1 * 8);
        cp16(bBase[b] + (uint32_t)(lrow0 * ASTRIDE + lcg0 * 8) * 2,
             Bsrc + (size_t)(n0 + lrow0) * E_ + kcol + lcg0 * 8);
        cp16(bBase[b] + (uint32_t)(lrow1 * ASTRIDE + lcg1 * 8) * 2,
             Bsrc + (size_t)(n0 + lrow1) * E_ + kcol + lcg1 * 8);
        asm volatile("cp.async.commit_group;" ::: "memory");
    };

    float acc[2][8][4];
    #pragma unroll
    for (int i = 0; i < 2; i++)
        #pragma unroll
        for (int j = 0; j < 8; j++)
            #pragma unroll
            for (int r = 0; r < 4; r++) acc[i][j][r] = 0.0f;

    issue_loads(0);

    for (int kc = 0; kc < NCHUNK; kc++) {
        const int b = kc & 1;
        if (kc + 1 < NCHUNK) {
            issue_loads(kc + 1);
            asm volatile("cp.async.wait_group 1;" ::: "memory");
        } else {
            asm volatile("cp.async.wait_group 0;" ::: "memory");
        }
        __syncthreads();

        #pragma unroll
        for (int ks = 0; ks < 2; ks++) {
            uint32_t afr[2][4];
            #pragma unroll
            for (int i = 0; i < 2; i++) {
                int row  = wm + i * 16 + (lane & 7) + ((lane >> 3) & 1) * 8;
                int half = lane >> 4;
                ldm_x4(afr[i], aBase[b] + row * (ASTRIDE * 2) + ks * 32 + half * 16);
            }
            uint32_t bfr[8][2];
            #pragma unroll
            for (int bj = 0; bj < 4; bj++) {
                int row  = wn + bj * 16 + (lane & 7) + (lane >> 4) * 8;
                int half = (lane >> 3) & 1;
                uint32_t q[4];
                ldm_x4(q, bBase[b] + row * (ASTRIDE * 2) + ks * 32 + half * 16);
                bfr[bj * 2][0] = q[0];     bfr[bj * 2][1] = q[1];
                bfr[bj * 2 + 1][0] = q[2]; bfr[bj * 2 + 1][1] = q[3];
            }
            #pragma unroll
            for (int i = 0; i < 2; i++)
                #pragma unroll
                for (int j = 0; j < 8; j++)
                    mma16816(acc[i][j], afr[i], bfr[j]);
        }
        __syncthreads();
    }

    const int gp   = lane >> 2;
    const int tid4 = lane & 3;
    #pragma unroll
    for (int j = 0; j < 8; j++) {
        const int n = n0 + wn + j * 8 + tid4 * 2;
        const float c0 = fmaf(3.0f, __ldg(&b1[n + 0]), __ldg(&coff[n + 0]));
        const float c1 = fmaf(3.0f, __ldg(&b1[n + 1]), __ldg(&coff[n + 1]));
        #pragma unroll
        for (int i = 0; i < 2; i++) {
            const int mrow = m0 + wm + i * 16 + gp;
            float2 v0, v1;
            v0.x = fmaf(3.0f, acc[i][j][0], c0);
            v0.y = fmaf(3.0f, acc[i][j][1], c1);
            v1.x = fmaf(3.0f, acc[i][j][2], c0);
            v1.y = fmaf(3.0f, acc[i][j][3], c1);
            *(float2*)&g_logits[(size_t)mrow * C_ + n]       = v0;
            *(float2*)&g_logits[(size_t)(mrow + 8) * C_ + n] = v1;
        }
    }
}

// ---------------- warp helpers ----------------
__device__ __forceinline__ int warp_argmax(float z, int lane) {
    float bv = z; int bi = lane;
    #pragma unroll
    for (int off = 16; off; off >>= 1) {
        float ov = __shfl_xor_sync(0xffffffffu, bv, off);
        int   oi = __shfl_xor_sync(0xffffffffu, bi, off);
        if (ov > bv || (ov == bv && oi < bi)) { bv = ov; bi = oi; }
    }
    return bi;
}
__device__ __forceinline__ int warp_argmax_m(float z, int lane, float* mar) {
    float bv = z; int bi = lane;
    #pragma unroll
    for (int off = 16; off; off >>= 1) {
        float ov = __shfl_xor_sync(0xffffffffu, bv, off);
        int   oi = __shfl_xor_sync(0xffffffffu, bi, off);
        if (ov > bv || (ov == bv && oi < bi)) { bv = ov; bi = oi; }
    }
    float z2 = (lane == bi) ? -3.4e38f : z;
    #pragma unroll
    for (int off = 16; off; off >>= 1)
        z2 = fmaxf(z2, __shfl_xor_sync(0xffffffffu, z2, off));
    *mar = bv - z2;
    return bi;
}

// ---------------- kernel 2: fused softmax/sample/gather/LN per token -------
__global__ void __launch_bounds__(256)
fused_k(const float* __restrict__ g1, const float* __restrict__ g2,
        const float* __restrict__ wI, const float* __restrict__ uI,
        const float* __restrict__ b2, const float* __restrict__ gamma,
        const float* __restrict__ beta,
        const float* __restrict__ x,  const float* __restrict__ W1,
        const float* __restrict__ b1, const float* __restrict__ coff,
        float* __restrict__ oSamp, float* __restrict__ oSoft,
        float* __restrict__ oPos,  float* __restrict__ oNeg)
{
    const int t    = blockIdx.x;
    const int tid  = threadIdx.x;
    const int lane = tid & 31;
    const int wid  = tid >> 5;

    __shared__ float sWt[2 * G_];     // [0:32) wi, [32:64) wj
    __shared__ int   sRow[2 * G_];    // [0:32) iA, [32:64) iB
    __shared__ float rbuf[18];

    const size_t baseC = (size_t)t * C_;

    // --- phase 1: per-group softmax + two Gumbel argmaxes + sparse sampled ---
    for (int g = wid; g < G_; g += 8) {
        const size_t idx = baseC + g * CG_ + lane;
        float v = g_logits[idx];
        float m = v;
        #pragma unroll
        for (int off = 16; off; off >>= 1)
            m = fmaxf(m, __shfl_xor_sync(0xffffffffu, m, off));
        float e = __expf(v - m);
        float s = e;
        #pragma unroll
        for (int off = 16; off; off >>= 1)
            s += __shfl_xor_sync(0xffffffffu, s, off);
        oSoft[idx] = e / s;

        float gu1 = __ldg(&g1[idx]);
        float gu2 = __ldg(&g2[idx]);
        float m1, m2;
        int i1 = warp_argmax_m(v + gu1, lane, &m1);
        int i2 = warp_argmax_m(v + gu2, lane, &m2);

        // Near-tie refinement: exact sequential-fmaf fp32 chain (k ascending),
        // bit-identical to the proven fp32 reference numerics.
        if (m1 < REFINE_THR || m2 < REFINE_THR) {
            const int cls = g * CG_ + lane;
            const float4* x4 = (const float4*)(x + (size_t)t * E_);
            const float4* w4 = (const float4*)(W1 + (size_t)cls * E_);
            float acc = 0.f;
            #pragma unroll 4
            for (int k = 0; k < E_ / 4; k++) {
                float4 a = __ldg(&x4[k]);
                float4 b = __ldg(&w4[k]);
                acc = fmaf(a.x, b.x, acc);
                acc = fmaf(a.y, b.y, acc);
                acc = fmaf(a.z, b.z, acc);
                acc = fmaf(a.w, b.w, acc);
            }
            float cb = fmaf(3.0f, __ldg(&b1[cls]), __ldg(&coff[cls]));
            float vr = fmaf(3.0f, acc, cb);
            i1 = warp_argmax(vr + gu1, lane);
            i2 = warp_argmax(vr + gu2, lane);
        }

        float w = __ldg(&wI[t * G_ + g]);
        float u = __ldg(&uI[t * G_ + g]);
        float cwi, cwj;
        if (u < 1.0f) { cwi = w;    cwj = 1.0f - w; }
        else          { cwi = 1.0f; cwj = 0.0f;     }

        float val = 0.0f;
        if (lane == i1) val += cwi;
        if (lane == i2) val += cwj;
        oSamp[idx] = val;

        if (lane == 0) {
            sRow[g]      = g * CG_ + i1;  sWt[g]      = cwi;
            sRow[G_ + g] = g * CG_ + i2;  sWt[G_ + g] = cwj;
        }
    }
    __syncthreads();

    // --- phase 2: sparse projection, float2 per thread, 4 independent chains
    const float2* W2T2 = (const float2*)g_W2T;   // row stride 256 float2
    float2 a0 = {0.f, 0.f}, a1 = {0.f, 0.f}, a2 = {0.f, 0.f}, a3 = {0.f, 0.f};
    #pragma unroll
    for (int p = 0; p < 16; p++) {
        int   r0 = sRow[p],       r1 = sRow[p + 16];
        int   r2 = sRow[p + 32],  r3 = sRow[p + 48];
        float w0 = sWt[p],        w1 = sWt[p + 16];
        float w2 = sWt[p + 32],   w3 = sWt[p + 48];
        float2 v0 = __ldg(&W2T2[(size_t)r0 * 256 + tid]);
        float2 v1 = __ldg(&W2T2[(size_t)r1 * 256 + tid]);
        float2 v2 = __ldg(&W2T2[(size_t)r2 * 256 + tid]);
        float2 v3 = __ldg(&W2T2[(size_t)r3 * 256 + tid]);
        a0.x = fmaf(w0, v0.x, a0.x); a0.y = fmaf(w0, v0.y, a0.y);
        a1.x = fmaf(w1, v1.x, a1.x); a1.y = fmaf(w1, v1.y, a1.y);
        a2.x = fmaf(w2, v2.x, a2.x); a2.y = fmaf(w2, v2.y, a2.y);
        a3.x = fmaf(w3, v3.x, a3.x); a3.y = fmaf(w3, v3.y, a3.y);
    }
    float2 bb = __ldg(&((const float2*)b2)[tid]);
    float accx = ((a0.x + a1.x) + (a2.x + a3.x)) + bb.x;
    float accy = ((a0.y + a1.y) + (a2.y + a3.y)) + bb.y;

    // --- phase 3: LayerNorm from registers ---
    float s_sum = accx + accy;
    float s_sq  = accx * accx + accy * accy;
    #pragma unroll
    for (int off = 16; off; off >>= 1) {
        s_sum += __shfl_xor_sync(0xffffffffu, s_sum, off);
        s_sq  += __shfl_xor_sync(0xffffffffu, s_sq,  off);
    }
    if (lane == 0) { rbuf[wid] = s_sum; rbuf[8 + wid] = s_sq; }
    __syncthreads();
    if (tid == 0) {
        float S = 0.f, S2 = 0.f;
        #pragma unroll
        for (int w = 0; w < 8; w++) { S += rbuf[w]; S2 += rbuf[8 + w]; }
        float mu  = S * (1.0f / E_);
        float var = S2 * (1.0f / E_) - mu * mu;
        rbuf[16] = mu;
        rbuf[17] = rsqrtf(var + LN_EPS);
    }
    __syncthreads();
    const float mu = rbuf[16], inv = rbuf[17];

    float2 gm = __ldg(&((const float2*)gamma)[tid]);
    float2 bt = __ldg(&((const float2*)beta)[tid]);
    float2 y;
    y.x = (accx - mu) * inv * gm.x + bt.x;
    y.y = (accy - mu) * inv * gm.y + bt.y;
    const size_t baseE2 = (size_t)t * (E_ / 2);
    ((float2*)oPos)[baseE2 + tid] = y;
    ((float2*)oNeg)[baseE2 + tid] = y;
}

// ---------------- launcher (pure kernel launches; graph-capture safe) ------
extern "C" void kernel_launch(void* const* d_in, const int* in_sizes, int n_in,
                              void* d_out, int out_size)
{
    const float* x     = (const float*)d_in[0];
    const float* W1    = (const float*)d_in[1];
    const float* b1    = (const float*)d_in[2];
    const float* coff  = (const float*)d_in[3];
    const float* W2    = (const float*)d_in[4];
    const float* b2    = (const float*)d_in[5];
    const float* gam   = (const float*)d_in[6];
    const float* bet   = (const float*)d_in[7];
    const float* g1    = (const float*)d_in[8];
    const float* g2    = (const float*)d_in[9];
    const float* wI    = (const float*)d_in[10];
    const float* uI    = (const float*)d_in[11];

    float* out     = (float*)d_out;
    float* o_samp  = out;
    float* o_soft  = out + (size_t)TOK_ * C_;
    float* o_pos   = out + (size_t)2 * TOK_ * C_;
    float* o_neg   = o_pos + (size_t)TOK_ * E_;

    transpose_k<<<dim3(C_ / 32, E_ / 32), dim3(32, 32)>>>(W2);
    split_x_k<<<(TOK_ * E_ / 4 + 255) / 256, 256>>>(x);
    split_w_k<<<(C_ * E_ / 4 + 255) / 256, 256>>>(W1);
    gemm_mma<<<dim3(C_ / BN, TOK_ / BM), 256>>>(b1, coff);
    fused_k<<<TOK_, 256>>>(g1, g2, wI, uI, b2, gam, bet,
                           x, W1, b1, coff,
                           o_samp, o_soft, o_pos, o_neg);
}

// round 11
// speedup vs baseline: 1.8568x; 1.2396x over previous
#include <cuda_runtime.h>
#include <cuda_fp16.h>
#include <cstdint>

// ---------------- problem constants ----------------
#define S_    2048
#define N_    8
#define E_    512
#define C_    1024
#define G_    32
#define CG_   32
#define TOK_  (S_ * N_)          // 16384 tokens
#define LN_EPS 1e-5f

// GEMM tiling (mma.sync path — tcgen05 unavailable on this toolchain)
#define BM 128
#define BN 128
#define BK 32
#define NCHUNK1 32                // gemm1: 2 fp16 split segments x (512/32)
#define NCHUNK2 32                // gemm2: K=1024 / 32
#define ASTRIDE 40                // smem row stride in fp16 elems (80 B)

// refinement trigger: fp16-2seg logit error bound ~8e-4 max; 5x headroom
#define REFINE_THR 4e-3f

// ---------------- scratch (device globals) --------
__device__ float  g_logits[(size_t)TOK_ * C_];         // 64 MB
__device__ __half g_Ahi[(size_t)TOK_ * E_];            // 16 MB
__device__ __half g_Alo[(size_t)TOK_ * E_];            // 16 MB
__device__ __half g_Bhi[(size_t)C_ * E_];              // 1 MB
__device__ __half g_sampH[(size_t)TOK_ * C_];          // 32 MB (fp16 sampled)
__device__ __half g_W2h[(size_t)E_ * C_];              // 1 MB  (fp16 W2, [e][c])
__device__ float  g_posPre[(size_t)TOK_ * E_];         // 32 MB (pre-LN projection)

// ---------------- helpers ----------------
__device__ __forceinline__ uint32_t smem_u32(const void* p) {
    uint32_t a;
    asm("{ .reg .u64 t; cvta.to.shared.u64 t, %1; cvt.u32.u64 %0, t; }"
        : "=r"(a) : "l"(p));
    return a;
}
__device__ __forceinline__ void cp16(uint32_t saddr, const void* gptr) {
    asm volatile("cp.async.cg.shared.global [%0], [%1], 16;"
                 :: "r"(saddr), "l"(gptr) : "memory");
}
__device__ __forceinline__ void ldm_x4(uint32_t* r, uint32_t addr) {
    asm volatile("ldmatrix.sync.aligned.m8n8.x4.shared.b16 {%0,%1,%2,%3}, [%4];"
                 : "=r"(r[0]), "=r"(r[1]), "=r"(r[2]), "=r"(r[3]) : "r"(addr));
}
__device__ __forceinline__ void mma16816(float* c, const uint32_t* a, const uint32_t* b) {
    asm volatile(
        "mma.sync.aligned.m16n8k16.row.col.f32.f16.f16.f32 "
        "{%0,%1,%2,%3}, {%4,%5,%6,%7}, {%8,%9}, {%0,%1,%2,%3};"
        : "+f"(c[0]), "+f"(c[1]), "+f"(c[2]), "+f"(c[3])
        : "r"(a[0]), "r"(a[1]), "r"(a[2]), "r"(a[3]), "r"(b[0]), "r"(b[1]));
}
// order-preserving float->u32 key (exact, monotone)
__device__ __forceinline__ uint32_t fkey(float f) {
    uint32_t b = __float_as_uint(f);
    return (b & 0x80000000u) ? ~b : (b | 0x80000000u);
}
__device__ __forceinline__ float funkey(uint32_t k) {
    uint32_t b = (k & 0x80000000u) ? (k & 0x7fffffffu) : ~k;
    return __uint_as_float(b);
}
__device__ __forceinline__ uint32_t redux_max_u32(uint32_t v) {
    uint32_t r;
    asm volatile("redux.sync.max.u32 %0, %1, 0xffffffff;" : "=r"(r) : "r"(v));
    return r;
}

// ---------------- kernel 0a: fp32 -> (fp16 hi, fp16 lo) split of x --------
__global__ void split_x_k(const float* __restrict__ in) {
    int i = blockIdx.x * 256 + threadIdx.x;
    if (i < TOK_ * E_ / 4) {
        float4 v = ((const float4*)in)[i];
        __half h0 = __float2half_rn(v.x), h1 = __float2half_rn(v.y);
        __half h2 = __float2half_rn(v.z), h3 = __float2half_rn(v.w);
        __half2 hi01, hi23, lo01, lo23;
        hi01.x = h0; hi01.y = h1; hi23.x = h2; hi23.y = h3;
        lo01.x = __float2half_rn(v.x - __half2float(h0));
        lo01.y = __float2half_rn(v.y - __half2float(h1));
        lo23.x = __float2half_rn(v.z - __half2float(h2));
        lo23.y = __float2half_rn(v.w - __half2float(h3));
        ((__half2*)g_Ahi)[i * 2]     = hi01;
        ((__half2*)g_Ahi)[i * 2 + 1] = hi23;
        ((__half2*)g_Alo)[i * 2]     = lo01;
        ((__half2*)g_Alo)[i * 2 + 1] = lo23;
    }
}
// ---------------- kernel 0b: W1 -> fp16 ------------------------------------
__global__ void split_w_k(const float* __restrict__ in) {
    int i = blockIdx.x * 256 + threadIdx.x;
    if (i < C_ * E_ / 4) {
        float4 v = ((const float4*)in)[i];
        __half2 hi01, hi23;
        hi01.x = __float2half_rn(v.x); hi01.y = __float2half_rn(v.y);
        hi23.x = __float2half_rn(v.z); hi23.y = __float2half_rn(v.w);
        ((__half2*)g_Bhi)[i * 2]     = hi01;
        ((__half2*)g_Bhi)[i * 2 + 1] = hi23;
    }
}
// ---------------- kernel 0c: W2 -> fp16 (layout kept: [e][c]) --------------
__global__ void w2h_k(const float* __restrict__ in) {
    int i = blockIdx.x * 256 + threadIdx.x;
    if (i < E_ * C_ / 4) {
        float4 v = ((const float4*)in)[i];
        __half2 h01, h23;
        h01.x = __float2half_rn(v.x); h01.y = __float2half_rn(v.y);
        h23.x = __float2half_rn(v.z); h23.y = __float2half_rn(v.w);
        ((__half2*)g_W2h)[i * 2]     = h01;
        ((__half2*)g_W2h)[i * 2 + 1] = h23;
    }
}

// ---------------- kernel 1: fp16 split-GEMM  logits = 3(xW1^T + b1) + coff -
__global__ void __launch_bounds__(256, 2)
gemm_mma(const float* __restrict__ b1, const float* __restrict__ coff)
{
    __shared__ __align__(16) __half sA[2][BM * ASTRIDE];
    __shared__ __align__(16) __half sB[2][BN * ASTRIDE];

    const int tid  = threadIdx.x;
    const int lane = tid & 31;
    const int wid  = tid >> 5;
    const int wm   = (wid & 3) * 32;
    const int wn   = (wid >> 2) * 64;
    const int m0   = blockIdx.y * BM;
    const int n0   = blockIdx.x * BN;

    const uint32_t aBase[2] = { smem_u32(&sA[0][0]), smem_u32(&sA[1][0]) };
    const uint32_t bBase[2] = { smem_u32(&sB[0][0]), smem_u32(&sB[1][0]) };

    const int lrow0 = tid >> 2,         lcg0 = (tid & 3);
    const int lrow1 = (tid + 256) >> 2, lcg1 = ((tid + 256) & 3);

    auto issue_loads = [&](int kc) {
        const int b   = kc & 1;
        const int seg = kc >> 4;
        const __half* Asrc = seg ? g_Alo : g_Ahi;
        const int kcol = (kc & 15) * BK;
        cp16(aBase[b] + (uint32_t)(lrow0 * ASTRIDE + lcg0 * 8) * 2,
             Asrc + (size_t)(m0 + lrow0) * E_ + kcol + lcg0 * 8);
        cp16(aBase[b] + (uint32_t)(lrow1 * ASTRIDE + lcg1 * 8) * 2,
             Asrc + (size_t)(m0 + lrow1) * E_ + kcol + lcg1 * 8);
        cp16(bBase[b] + (uint32_t)(lrow0 * ASTRIDE + lcg0 * 8) * 2,
             g_Bhi + (size_t)(n0 + lrow0) * E_ + kcol + lcg0 * 8);
        cp16(bBase[b] + (uint32_t)(lrow1 * ASTRIDE + lcg1 * 8) * 2,
             g_Bhi + (size_t)(n0 + lrow1) * E_ + kcol + lcg1 * 8);
        asm volatile("cp.async.commit_group;" ::: "memory");
    };

    float acc[2][8][4];
    #pragma unroll
    for (int i = 0; i < 2; i++)
        #pragma unroll
        for (int j = 0; j < 8; j++)
            #pragma unroll
            for (int r = 0; r < 4; r++) acc[i][j][r] = 0.0f;

    issue_loads(0);

    for (int kc = 0; kc < NCHUNK1; kc++) {
        const int b = kc & 1;
        if (kc + 1 < NCHUNK1) {
            issue_loads(kc + 1);
            asm volatile("cp.async.wait_group 1;" ::: "memory");
        } else {
            asm volatile("cp.async.wait_group 0;" ::: "memory");
        }
        __syncthreads();

        #pragma unroll
        for (int ks = 0; ks < 2; ks++) {
            uint32_t afr[2][4];
            #pragma unroll
            for (int i = 0; i < 2; i++) {
                int row  = wm + i * 16 + (lane & 7) + ((lane >> 3) & 1) * 8;
                int half = lane >> 4;
                ldm_x4(afr[i], aBase[b] + row * (ASTRIDE * 2) + ks * 32 + half * 16);
            }
            uint32_t bfr[8][2];
            #pragma unroll
            for (int bj = 0; bj < 4; bj++) {
                int row  = wn + bj * 16 + (lane & 7) + (lane >> 4) * 8;
                int half = (lane >> 3) & 1;
                uint32_t q[4];
                ldm_x4(q, bBase[b] + row * (ASTRIDE * 2) + ks * 32 + half * 16);
                bfr[bj * 2][0] = q[0];     bfr[bj * 2][1] = q[1];
                bfr[bj * 2 + 1][0] = q[2]; bfr[bj * 2 + 1][1] = q[3];
            }
            #pragma unroll
            for (int i = 0; i < 2; i++)
                #pragma unroll
                for (int j = 0; j < 8; j++)
                    mma16816(acc[i][j], afr[i], bfr[j]);
        }
        __syncthreads();
    }

    const int gp   = lane >> 2;
    const int tid4 = lane & 3;
    #pragma unroll
    for (int j = 0; j < 8; j++) {
        const int n = n0 + wn + j * 8 + tid4 * 2;
        const float c0 = fmaf(3.0f, __ldg(&b1[n + 0]), __ldg(&coff[n + 0]));
        const float c1 = fmaf(3.0f, __ldg(&b1[n + 1]), __ldg(&coff[n + 1]));
        #pragma unroll
        for (int i = 0; i < 2; i++) {
            const int mrow = m0 + wm + i * 16 + gp;
            float2 v0, v1;
            v0.x = fmaf(3.0f, acc[i][j][0], c0);
            v0.y = fmaf(3.0f, acc[i][j][1], c1);
            v1.x = fmaf(3.0f, acc[i][j][2], c0);
            v1.y = fmaf(3.0f, acc[i][j][3], c1);
            *(float2*)&g_logits[(size_t)mrow * C_ + n]       = v0;
            *(float2*)&g_logits[(size_t)(mrow + 8) * C_ + n] = v1;
        }
    }
}

// ---------------- kernel 3: fp16 GEMM  posPre = sampH @ W2h^T + b2 ---------
// A = g_sampH [TOK, C] row-major; B = g_W2h [E, C] row-major (N=E, K=C)
__global__ void __launch_bounds__(256, 2)
gemm2_mma(const float* __restrict__ b2)
{
    __shared__ __align__(16) __half sA[2][BM * ASTRIDE];
    __shared__ __align__(16) __half sB[2][BN * ASTRIDE];

    const int tid  = threadIdx.x;
    const int lane = tid & 31;
    const int wid  = tid >> 5;
    const int wm   = (wid & 3) * 32;
    const int wn   = (wid >> 2) * 64;
    const int m0   = blockIdx.y * BM;
    const int n0   = blockIdx.x * BN;

    const uint32_t aBase[2] = { smem_u32(&sA[0][0]), smem_u32(&sA[1][0]) };
    const uint32_t bBase[2] = { smem_u32(&sB[0][0]), smem_u32(&sB[1][0]) };

    const int lrow0 = tid >> 2,         lcg0 = (tid & 3);
    const int lrow1 = (tid + 256) >> 2, lcg1 = ((tid + 256) & 3);

    auto issue_loads = [&](int kc) {
        const int b    = kc & 1;
        const int kcol = kc * BK;
        cp16(aBase[b] + (uint32_t)(lrow0 * ASTRIDE + lcg0 * 8) * 2,
             g_sampH + (size_t)(m0 + lrow0) * C_ + kcol + lcg0 * 8);
        cp16(aBase[b] + (uint32_t)(lrow1 * ASTRIDE + lcg1 * 8) * 2,
             g_sampH + (size_t)(m0 + lrow1) * C_ + kcol + lcg1 * 8);
        cp16(bBase[b] + (uint32_t)(lrow0 * ASTRIDE + lcg0 * 8) * 2,
             g_W2h + (size_t)(n0 + lrow0) * C_ + kcol + lcg0 * 8);
        cp16(bBase[b] + (uint32_t)(lrow1 * ASTRIDE + lcg1 * 8) * 2,
             g_W2h + (size_t)(n0 + lrow1) * C_ + kcol + lcg1 * 8);
        asm volatile("cp.async.commit_group;" ::: "memory");
    };

    float acc[2][8][4];
    #pragma unroll
    for (int i = 0; i < 2; i++)
        #pragma unroll
        for (int j = 0; j < 8; j++)
            #pragma unroll
            for (int r = 0; r < 4; r++) acc[i][j][r] = 0.0f;

    issue_loads(0);

    for (int kc = 0; kc < NCHUNK2; kc++) {
        const int b = kc & 1;
        if (kc + 1 < NCHUNK2) {
            issue_loads(kc + 1);
            asm volatile("cp.async.wait_group 1;" ::: "memory");
        } else {
            asm volatile("cp.async.wait_group 0;" ::: "memory");
        }
        __syncthreads();

        #pragma unroll
        for (int ks = 0; ks < 2; ks++) {
            uint32_t afr[2][4];
            #pragma unroll
            for (int i = 0; i < 2; i++) {
                int row  = wm + i * 16 + (lane & 7) + ((lane >> 3) & 1) * 8;
                int half = lane >> 4;
                ldm_x4(afr[i], aBase[b] + row * (ASTRIDE * 2) + ks * 32 + half * 16);
            }
            uint32_t bfr[8][2];
            #pragma unroll
            for (int bj = 0; bj < 4; bj++) {
                int row  = wn + bj * 16 + (lane & 7) + (lane >> 4) * 8;
                int half = (lane >> 3) & 1;
                uint32_t q[4];
                ldm_x4(q, bBase[b] + row * (ASTRIDE * 2) + ks * 32 + half * 16);
                bfr[bj * 2][0] = q[0];     bfr[bj * 2][1] = q[1];
                bfr[bj * 2 + 1][0] = q[2]; bfr[bj * 2 + 1][1] = q[3];
            }
            #pragma unroll
            for (int i = 0; i < 2; i++)
                #pragma unroll
                for (int j = 0; j < 8; j++)
                    mma16816(acc[i][j], afr[i], bfr[j]);
        }
        __syncthreads();
    }

    const int gp   = lane >> 2;
    const int tid4 = lane & 3;
    #pragma unroll
    for (int j = 0; j < 8; j++) {
        const int n = n0 + wn + j * 8 + tid4 * 2;
        const float c0 = __ldg(&b2[n + 0]);
        const float c1 = __ldg(&b2[n + 1]);
        #pragma unroll
        for (int i = 0; i < 2; i++) {
            const int mrow = m0 + wm + i * 16 + gp;
            float2 v0, v1;
            v0.x = acc[i][j][0] + c0;
            v0.y = acc[i][j][1] + c1;
            v1.x = acc[i][j][2] + c0;
            v1.y = acc[i][j][3] + c1;
            *(float2*)&g_posPre[(size_t)mrow * E_ + n]       = v0;
            *(float2*)&g_posPre[(size_t)(mrow + 8) * E_ + n] = v1;
        }
    }
}

// ---------------- warp helper (refinement path only) ----------------------
__device__ __forceinline__ int warp_argmax(float z, int lane) {
    float bv = z; int bi = lane;
    #pragma unroll
    for (int off = 16; off; off >>= 1) {
        float ov = __shfl_xor_sync(0xffffffffu, bv, off);
        int   oi = __shfl_xor_sync(0xffffffffu, bi, off);
        if (ov > bv || (ov == bv && oi < bi)) { bv = ov; bi = oi; }
    }
    return bi;
}

// ---------------- kernel 2: softmax + Gumbel sampling per token ------------
__global__ void __launch_bounds__(256)
samp_k(const float* __restrict__ g1, const float* __restrict__ g2,
       const float* __restrict__ wI, const float* __restrict__ uI,
       const float* __restrict__ x,  const float* __restrict__ W1,
       const float* __restrict__ b1, const float* __restrict__ coff,
       float* __restrict__ oSamp, float* __restrict__ oSoft)
{
    const int t    = blockIdx.x;
    const int tid  = threadIdx.x;
    const int lane = tid & 31;
    const int wid  = tid >> 5;

    const size_t baseC = (size_t)t * C_;

    for (int g = wid; g < G_; g += 8) {
        const size_t idx = baseC + g * CG_ + lane;
        float v = g_logits[idx];

        // softmax: exact max via redux on order-preserving key
        float m = funkey(redux_max_u32(fkey(v)));
        float e = __expf(v - m);
        float s = e;
        #pragma unroll
        for (int off = 16; off; off >>= 1)
            s += __shfl_xor_sync(0xffffffffu, s, off);
        oSoft[idx] = e / s;

        float gu1 = __ldg(&g1[idx]);
        float gu2 = __ldg(&g2[idx]);

        // argmax + margin via redux/ballot (exact; lowest-index tie)
        float z1 = v + gu1;
        uint32_t k1 = fkey(z1);
        uint32_t km1 = redux_max_u32(k1);
        int i1 = __ffs(__ballot_sync(0xffffffffu, k1 == km1)) - 1;
        float m1 = funkey(km1) - funkey(redux_max_u32(lane == i1 ? 0u : k1));

        float z2 = v + gu2;
        uint32_t k2 = fkey(z2);
        uint32_t km2 = redux_max_u32(k2);
        int i2 = __ffs(__ballot_sync(0xffffffffu, k2 == km2)) - 1;
        float m2 = funkey(km2) - funkey(redux_max_u32(lane == i2 ? 0u : k2));

        // Near-tie refinement: exact sequential-fmaf fp32 chain (k ascending),
        // bit-identical to the proven fp32 reference numerics.
        if (m1 < REFINE_THR || m2 < REFINE_THR) {
            const int cls = g * CG_ + lane;
            const float4* x4 = (const float4*)(x + (size_t)t * E_);
            const float4* w4 = (const float4*)(W1 + (size_t)cls * E_);
            float acc = 0.f;
            #pragma unroll 4
            for (int k = 0; k < E_ / 4; k++) {
                float4 a = __ldg(&x4[k]);
                float4 b = __ldg(&w4[k]);
                acc = fmaf(a.x, b.x, acc);
                acc = fmaf(a.y, b.y, acc);
                acc = fmaf(a.z, b.z, acc);
                acc = fmaf(a.w, b.w, acc);
            }
            float cb = fmaf(3.0f, __ldg(&b1[cls]), __ldg(&coff[cls]));
            float vr = fmaf(3.0f, acc, cb);
            i1 = warp_argmax(vr + gu1, lane);
            i2 = warp_argmax(vr + gu2, lane);
        }

        float w = __ldg(&wI[t * G_ + g]);
        float u = __ldg(&uI[t * G_ + g]);
        float cwi, cwj;
        if (u < 1.0f) { cwi = w;    cwj = 1.0f - w; }
        else          { cwi = 1.0f; cwj = 0.0f;     }

        float val = 0.0f;
        if (lane == i1) val += cwi;
        if (lane == i2) val += cwj;
        oSamp[idx]  = val;
        g_sampH[idx] = __float2half_rn(val);
    }
}

// ---------------- kernel 4: LayerNorm over posPre -> oPos, oNeg ------------
__global__ void __launch_bounds__(256)
ln_k(const float* __restrict__ gamma, const float* __restrict__ beta,
     float* __restrict__ oPos, float* __restrict__ oNeg)
{
    const int t    = blockIdx.x;
    const int tid  = threadIdx.x;
    const int lane = tid & 31;
    const int wid  = tid >> 5;
    __shared__ float rbuf[18];

    float2 v = ((const float2*)g_posPre)[(size_t)t * 256 + tid];

    float s_sum = v.x + v.y;
    float s_sq  = v.x * v.x + v.y * v.y;
    #pragma unroll
    for (int off = 16; off; off >>= 1) {
        s_sum += __shfl_xor_sync(0xffffffffu, s_sum, off);
        s_sq  += __shfl_xor_sync(0xffffffffu, s_sq,  off);
    }
    if (lane == 0) { rbuf[wid] = s_sum; rbuf[8 + wid] = s_sq; }
    __syncthreads();
    if (tid == 0) {
        float S = 0.f, S2 = 0.f;
        #pragma unroll
        for (int w = 0; w < 8; w++) { S += rbuf[w]; S2 += rbuf[8 + w]; }
        float mu  = S * (1.0f / E_);
        float var = S2 * (1.0f / E_) - mu * mu;
        rbuf[16] = mu;
        rbuf[17] = rsqrtf(var + LN_EPS);
    }
    __syncthreads();
    const float mu = rbuf[16], inv = rbuf[17];

    float2 gm = __ldg(&((const float2*)gamma)[tid]);
    float2 bt = __ldg(&((const float2*)beta)[tid]);
    float2 y;
    y.x = (v.x - mu) * inv * gm.x + bt.x;
    y.y = (v.y - mu) * inv * gm.y + bt.y;
    const size_t baseE2 = (size_t)t * 256;
    ((float2*)oPos)[baseE2 + tid] = y;
    ((float2*)oNeg)[baseE2 + tid] = y;
}

// ---------------- launcher (pure kernel launches; graph-capture safe) ------
extern "C" void kernel_launch(void* const* d_in, const int* in_sizes, int n_in,
                              void* d_out, int out_size)
{
    const float* x     = (const float*)d_in[0];
    const float* W1    = (const float*)d_in[1];
    const float* b1    = (const float*)d_in[2];
    const float* coff  = (const float*)d_in[3];
    const float* W2    = (const float*)d_in[4];
    const float* b2    = (const float*)d_in[5];
    const float* gam   = (const float*)d_in[6];
    const float* bet   = (const float*)d_in[7];
    const float* g1    = (const float*)d_in[8];
    const float* g2    = (const float*)d_in[9];
    const float* wI    = (const float*)d_in[10];
    const float* uI    = (const float*)d_in[11];

    float* out     = (float*)d_out;
    float* o_samp  = out;
    float* o_soft  = out + (size_t)TOK_ * C_;
    float* o_pos   = out + (size_t)2 * TOK_ * C_;
    float* o_neg   = o_pos + (size_t)TOK_ * E_;

    split_x_k<<<(TOK_ * E_ / 4 + 255) / 256, 256>>>(x);
    split_w_k<<<(C_ * E_ / 4 + 255) / 256, 256>>>(W1);
    w2h_k<<<(E_ * C_ / 4 + 255) / 256, 256>>>(W2);
    gemm_mma<<<dim3(C_ / BN, TOK_ / BM), 256>>>(b1, coff);
    samp_k<<<TOK_, 256>>>(g1, g2, wI, uI, x, W1, b1, coff, o_samp, o_soft);
    gemm2_mma<<<dim3(E_ / BN, TOK_ / BM), 256>>>(b2);
    ln_k<<<TOK_, 256>>>(gam, bet, o_pos, o_neg);
}